// round 17
// baseline (speedup 1.0000x reference)
#include <cuda_runtime.h>
#include <cuda_bf16.h>
#include <cstdint>
#include <math.h>

#define TTOK 8192
#define DDIM 1024
#define HDIM 1408
#define NE   8

// ---- static device scratch ----
__device__ int    g_ecount[NE];
__device__ int    g_etok[NE][TTOK];
__device__ float  g_ew[NE][TTOK];
__device__ double g_usage[NE];
__device__ __align__(256) __nv_bfloat16 g_xh[(size_t)TTOK * DDIM];
__device__ __align__(256) __nv_bfloat16 g_xl[(size_t)TTOK * DDIM];
__device__ __align__(256) __nv_bfloat16 g_hh[(size_t)NE * TTOK * HDIM];
__device__ __align__(256) __nv_bfloat16 g_hl[(size_t)NE * TTOK * HDIM];
__device__ __align__(256) __nv_bfloat16 g_wg[(size_t)NE * 2 * HDIM * DDIM];
__device__ __align__(256) __nv_bfloat16 g_wu[(size_t)NE * 2 * HDIM * DDIM];
__device__ __align__(256) __nv_bfloat16 g_wx[(size_t)NE * 2 * HDIM * DDIM];
__device__ __align__(256) __nv_bfloat16 g_wd[(size_t)NE * 2 * DDIM * HDIM];

__device__ __forceinline__ __nv_bfloat16* wsel_dst(int which) {
    switch (which) {
        case 0:  return g_wg;
        case 1:  return g_wu;
        case 2:  return g_wx;
        default: return g_wd;
    }
}

// ---- helpers ----
__device__ __forceinline__ uint32_t smem_u32(const void* p) {
    uint32_t a;
    asm("{ .reg .u64 t; cvta.to.shared.u64 t, %1; cvt.u32.u64 %0, t; }" : "=r"(a) : "l"(p));
    return a;
}
__device__ __forceinline__ void cpa16(uint32_t s, const void* g) {
    asm volatile("cp.async.cg.shared.global [%0], [%1], 16;" :: "r"(s), "l"(g));
}
#define CP_COMMIT() asm volatile("cp.async.commit_group;" ::: "memory")
#define CP_WAIT1()  asm volatile("cp.async.wait_group 1;" ::: "memory")
#define CP_WAIT0()  asm volatile("cp.async.wait_group 0;" ::: "memory")

__device__ __forceinline__ void mma_acc(float* d, const uint32_t* a, uint32_t b0, uint32_t b1) {
    asm volatile("mma.sync.aligned.m16n8k16.row.col.f32.bf16.bf16.f32 "
        "{%0,%1,%2,%3}, {%4,%5,%6,%7}, {%8,%9}, {%0,%1,%2,%3};"
        : "+f"(d[0]), "+f"(d[1]), "+f"(d[2]), "+f"(d[3])
        : "r"(a[0]), "r"(a[1]), "r"(a[2]), "r"(a[3]), "r"(b0), "r"(b1));
}
#define LDSM4(r0, r1, r2, r3, a) \
    asm volatile("ldmatrix.sync.aligned.m8n8.x4.shared.b16 {%0,%1,%2,%3}, [%4];" \
        : "=r"(r0), "=r"(r1), "=r"(r2), "=r"(r3) : "r"(a))

__device__ __forceinline__ uint32_t pack_hi(float a, float b, uint32_t& lo) {
    __nv_bfloat16 ha = __float2bfloat16(a), hb = __float2bfloat16(b);
    __nv_bfloat16 la = __float2bfloat16(a - __bfloat162float(ha));
    __nv_bfloat16 lb = __float2bfloat16(b - __bfloat162float(hb));
    lo = ((uint32_t)__bfloat16_as_ushort(lb) << 16) | __bfloat16_as_ushort(la);
    return ((uint32_t)__bfloat16_as_ushort(hb) << 16) | __bfloat16_as_ushort(ha);
}

// ================= K0 =================
__global__ void k_init(float* __restrict__ out) {
    int i = blockIdx.x * 256 + threadIdx.x;
    if (i < TTOK * DDIM) out[i] = 0.f;
    if (i < NE) { g_ecount[i] = 0; g_usage[i] = 0.0; }
}

// ===== K1: x -> bf16 hi/lo planes =====
__global__ void k_splitx(const float* __restrict__ x) {
    size_t i = ((size_t)blockIdx.x * 256 + threadIdx.x) * 4;
    if (i >= (size_t)TTOK * DDIM) return;
    float4 v = *(const float4*)(x + i);
    uint32_t l0, l1;
    uint32_t h0 = pack_hi(v.x, v.y, l0);
    uint32_t h1 = pack_hi(v.z, v.w, l1);
    *(uint32_t*)&g_xh[i]     = h0;
    *(uint32_t*)&g_xh[i + 2] = h1;
    *(uint32_t*)&g_xl[i]     = l0;
    *(uint32_t*)&g_xl[i + 2] = l1;
}

// ===== K2: transpose + split weights =====
__global__ void k_tsplit(const float* __restrict__ src, int which, int K, int N) {
    __shared__ float t[32][33];
    __nv_bfloat16* dst = wsel_dst(which);
    int e = blockIdx.z;
    int n0 = blockIdx.x * 32, k0 = blockIdx.y * 32;
    int tx = threadIdx.x, ty = threadIdx.y;
    const float* s = src + (size_t)e * K * N;
#pragma unroll
    for (int i = 0; i < 32; i += 8)
        t[ty + i][tx] = s[(size_t)(k0 + ty + i) * N + n0 + tx];
    __syncthreads();
    size_t pl = (size_t)K * N;
    size_t b0 = (size_t)e * 2 * pl;
#pragma unroll
    for (int i = 0; i < 32; i += 8) {
        float v = t[tx][ty + i];
        __nv_bfloat16 hi = __float2bfloat16(v);
        __nv_bfloat16 lo = __float2bfloat16(v - __bfloat162float(hi));
        size_t o = b0 + (size_t)(n0 + ty + i) * K + (k0 + tx);
        dst[o] = hi; dst[o + pl] = lo;
    }
}

// ===== K3: router (proven) =====
__global__ void __launch_bounds__(128) k_router(const float* __restrict__ x,
                                                const float* __restrict__ Wr) {
    __shared__ float us[NE];
    int tid = threadIdx.x;
    if (tid < NE) us[tid] = 0.f;
    __syncthreads();
    int warp = tid >> 5, lane = tid & 31;
    int t = blockIdx.x * 4 + warp;
    float acc[NE];
#pragma unroll
    for (int e = 0; e < NE; e++) acc[e] = 0.f;
    const float* xr = x + (size_t)t * DDIM;
    for (int d = lane; d < DDIM; d += 32) {
        float xv = xr[d];
        const float* wr = Wr + d * NE;
#pragma unroll
        for (int e = 0; e < NE; e++) acc[e] += xv * wr[e];
    }
#pragma unroll
    for (int off = 16; off; off >>= 1)
#pragma unroll
        for (int e = 0; e < NE; e++)
            acc[e] += __shfl_xor_sync(0xffffffffu, acc[e], off);
    if (lane == 0) {
        float m = acc[0];
#pragma unroll
        for (int e = 1; e < NE; e++) m = fmaxf(m, acc[e]);
        float p[NE], s = 0.f;
#pragma unroll
        for (int e = 0; e < NE; e++) { p[e] = __expf(acc[e] - m); s += p[e]; }
        float inv = 1.f / s;
#pragma unroll
        for (int e = 0; e < NE; e++) p[e] *= inv;
#pragma unroll
        for (int e = 0; e < NE; e++) atomicAdd(&us[e], p[e]);
        int i0 = 0;
#pragma unroll
        for (int e = 1; e < NE; e++) if (p[e] > p[i0]) i0 = e;
        int i1 = -1;
#pragma unroll
        for (int e = 0; e < NE; e++)
            if (e != i0 && (i1 < 0 || p[e] > p[i1])) i1 = e;
        float den = 1.f / (p[i0] + p[i1]);
        int pos0 = atomicAdd(&g_ecount[i0], 1);
        g_etok[i0][pos0] = t; g_ew[i0][pos0] = p[i0] * den;
        int pos1 = atomicAdd(&g_ecount[i1], 1);
        g_etok[i1][pos1] = t; g_ew[i1][pos1] = p[i1] * den;
    }
    __syncthreads();
    if (tid < NE) atomicAdd(&g_usage[tid], (double)us[tid]);
}

// ============================================================
// Fast upgate: 2 mats, cp.async double buffer, ldmatrix.
// sA [2buf][2pl][128][40] = 20480 sh; sB [2buf][2mat][2pl][64][40] = 20480 sh.
// ============================================================
__device__ void upgate_fast(unsigned short* sbuf, int e, int count, int row0, int n0,
                            const __nv_bfloat16* __restrict__ w2, float coef) {
    const int ST = 40;
    unsigned short* sA = sbuf;
    unsigned short* sB = sbuf + 20480;
    int tid = threadIdx.x, lane = tid & 31, w = tid >> 5;
    int wM = w & 3, wN = w >> 2;
    int g = lane >> 2, tig = lane & 3;
    int i8 = lane & 7, seg = lane >> 3;

    int ar = tid >> 1, kh = (tid & 1) * 16;
    int tok = g_etok[e][row0 + ar];
    const __nv_bfloat16* axh = g_xh + (size_t)tok * DDIM + kh;
    const __nv_bfloat16* axl = g_xl + (size_t)tok * DDIM + kh;
    int br = tid >> 2, bk = (tid & 3) * 8;
    const __nv_bfloat16* bsrc[2][2];
    bsrc[0][0] = g_wu + ((size_t)(e * 2 + 0) * HDIM + n0 + br) * DDIM + bk;
    bsrc[0][1] = g_wu + ((size_t)(e * 2 + 1) * HDIM + n0 + br) * DDIM + bk;
    bsrc[1][0] = w2   + ((size_t)(e * 2 + 0) * HDIM + n0 + br) * DDIM + bk;
    bsrc[1][1] = w2   + ((size_t)(e * 2 + 1) * HDIM + n0 + br) * DDIM + bk;

    uint32_t sAu = smem_u32(sA), sBu = smem_u32(sB);
    int arow_l = (seg & 1) * 8 + i8;
    int acol_l = (seg >> 1) * 8;
    int brow_l = (seg >> 1) * 8 + i8;
    int bcol_l = (seg & 1) * 8;

    float acc[2][2][4][4];
#pragma unroll
    for (int j = 0; j < 2; j++)
#pragma unroll
        for (int mf = 0; mf < 2; mf++)
#pragma unroll
            for (int nf = 0; nf < 4; nf++)
#pragma unroll
                for (int q = 0; q < 4; q++) acc[j][mf][nf][q] = 0.f;

    auto pf = [&](int buf, int k0) {
#pragma unroll
        for (int p = 0; p < 2; p++) {
            const __nv_bfloat16* s = (p ? axl : axh) + k0;
            uint32_t d = sAu + 2u * (uint32_t)(((buf * 2 + p) * 128 + ar) * ST + kh);
            cpa16(d, s); cpa16(d + 16, s + 8);
        }
#pragma unroll
        for (int j = 0; j < 2; j++)
#pragma unroll
            for (int p = 0; p < 2; p++)
                cpa16(sBu + 2u * (uint32_t)((((buf * 2 + j) * 2 + p) * 64 + br) * ST + bk),
                      bsrc[j][p] + k0);
    };

    const int NK = DDIM / 32;
    pf(0, 0);  CP_COMMIT();
    pf(1, 32); CP_COMMIT();

    for (int c = 0; c < NK; c++) {
        if (c + 1 < NK) CP_WAIT1(); else CP_WAIT0();
        __syncthreads();
        int buf = c & 1;
#pragma unroll
        for (int kk = 0; kk < 2; kk++) {
            uint32_t aF[2][2][4];
#pragma unroll
            for (int p = 0; p < 2; p++)
#pragma unroll
                for (int mf = 0; mf < 2; mf++) {
                    uint32_t ad = sAu + 2u * (uint32_t)(((buf * 2 + p) * 128 + wM * 32 + mf * 16 + arow_l) * ST + kk * 16 + acol_l);
                    LDSM4(aF[p][mf][0], aF[p][mf][1], aF[p][mf][2], aF[p][mf][3], ad);
                }
#pragma unroll
            for (int j = 0; j < 2; j++) {
                uint32_t bF[2][4][2];
#pragma unroll
                for (int p = 0; p < 2; p++)
#pragma unroll
                    for (int nfp = 0; nfp < 2; nfp++) {
                        uint32_t bd = sBu + 2u * (uint32_t)((((buf * 2 + j) * 2 + p) * 64 + wN * 32 + nfp * 16 + brow_l) * ST + kk * 16 + bcol_l);
                        LDSM4(bF[p][nfp * 2][0], bF[p][nfp * 2][1],
                              bF[p][nfp * 2 + 1][0], bF[p][nfp * 2 + 1][1], bd);
                    }
#pragma unroll
                for (int nf = 0; nf < 4; nf++)
#pragma unroll
                    for (int mf = 0; mf < 2; mf++) {
                        mma_acc(acc[j][mf][nf], aF[0][mf], bF[0][nf][0], bF[0][nf][1]);
                        mma_acc(acc[j][mf][nf], aF[0][mf], bF[1][nf][0], bF[1][nf][1]);
                        mma_acc(acc[j][mf][nf], aF[1][mf], bF[0][nf][0], bF[0][nf][1]);
                    }
            }
        }
        __syncthreads();
        if (c + 2 < NK) { pf(buf, (c + 2) * 32); CP_COMMIT(); }
    }

    // epilogue -> bf16 hi/lo h planes
#pragma unroll
    for (int mf = 0; mf < 2; mf++)
#pragma unroll
        for (int nf = 0; nf < 4; nf++) {
            int col = n0 + wN * 32 + nf * 8 + tig * 2;
#pragma unroll
            for (int hh = 0; hh < 2; hh++) {
                int rl = row0 + wM * 32 + mf * 16 + g + hh * 8;
                if (rl < count) {
                    float wc = g_ew[e][rl];
                    float u0 = acc[0][mf][nf][hh * 2 + 0], s0 = acc[1][mf][nf][hh * 2 + 0];
                    float u1 = acc[0][mf][nf][hh * 2 + 1], s1 = acc[1][mf][nf][hh * 2 + 1];
                    float v0 = wc * u0 * coef * (s0 * (1.f / (1.f + __expf(-s0))));
                    float v1 = wc * u1 * coef * (s1 * (1.f / (1.f + __expf(-s1))));
                    uint32_t lo;
                    uint32_t hi = pack_hi(v0, v1, lo);
                    size_t idx = (size_t)(e * TTOK + rl) * HDIM + col;
                    *(uint32_t*)&g_hh[idx] = hi;
                    *(uint32_t*)&g_hl[idx] = lo;
                }
            }
        }
}

// ============================================================
// Generic upgate (alpha not in {0,1}): R14-proven scalar path.
// ============================================================
#define GSA(p, r, k)    ((((p) * 128) + (r)) * 36 + (k))
#define GSB(j, p, r, k) ((((((j) * 2) + (p)) * 64) + (r)) * 36 + (k))
__device__ void upgate_gen(unsigned short* sbuf, const float* __restrict__ xg,
                           int e, int count, int row0, int n0, float al) {
    unsigned short* sA = sbuf;
    unsigned short* sB = sbuf + 9216;
    const __nv_bfloat16* wsl[3] = { g_wu, g_wg, g_wx };
    int tid = threadIdx.x, lane = tid & 31, w = tid >> 5;
    int wM = w & 3, wN = w >> 2;
    int g = lane >> 2, tig = lane & 3;
    int ar = tid >> 1, ahalf = (tid & 1) * 16;
    int tok = g_etok[e][row0 + ar];
    const float* asrc = xg + (size_t)tok * DDIM + ahalf;
    int br = tid >> 2, bk = (tid & 3) * 8;

    float4 aR[4];
    uint4  bR[3][2];
    float acc[3][2][4][4];
#pragma unroll
    for (int j = 0; j < 3; j++)
#pragma unroll
        for (int mf = 0; mf < 2; mf++)
#pragma unroll
            for (int nf = 0; nf < 4; nf++)
#pragma unroll
                for (int q = 0; q < 4; q++) acc[j][mf][nf][q] = 0.f;

#pragma unroll
    for (int q = 0; q < 4; q++) aR[q] = *(const float4*)(asrc + q * 4);
#pragma unroll
    for (int j = 0; j < 3; j++)
#pragma unroll
        for (int p = 0; p < 2; p++)
            bR[j][p] = *(const uint4*)(wsl[j] + ((size_t)(e * 2 + p) * HDIM + n0 + br) * DDIM + bk);

    const int NK = DDIM / 32;
    for (int c = 0; c < NK; c++) {
#pragma unroll
        for (int q = 0; q < 4; q++) {
            uint32_t l0, l1;
            uint32_t h0 = pack_hi(aR[q].x, aR[q].y, l0);
            uint32_t h1 = pack_hi(aR[q].z, aR[q].w, l1);
            int k = ahalf + q * 4;
            *(uint32_t*)&sA[GSA(0, ar, k)]     = h0;
            *(uint32_t*)&sA[GSA(0, ar, k + 2)] = h1;
            *(uint32_t*)&sA[GSA(1, ar, k)]     = l0;
            *(uint32_t*)&sA[GSA(1, ar, k + 2)] = l1;
        }
#pragma unroll
        for (int j = 0; j < 3; j++)
#pragma unroll
            for (int p = 0; p < 2; p++) {
                *(uint32_t*)&sB[GSB(j, p, br, bk)]     = bR[j][p].x;
                *(uint32_t*)&sB[GSB(j, p, br, bk + 2)] = bR[j][p].y;
                *(uint32_t*)&sB[GSB(j, p, br, bk + 4)] = bR[j][p].z;
                *(uint32_t*)&sB[GSB(j, p, br, bk + 6)] = bR[j][p].w;
            }
        __syncthreads();

        if (c + 1 < NK) {
            int k0 = (c + 1) * 32;
#pragma unroll
            for (int q = 0; q < 4; q++) aR[q] = *(const float4*)(asrc + k0 + q * 4);
#pragma unroll
            for (int j = 0; j < 3; j++)
#pragma unroll
                for (int p = 0; p < 2; p++)
                    bR[j][p] = *(const uint4*)(wsl[j] + ((size_t)(e * 2 + p) * HDIM + n0 + br) * DDIM + k0 + bk);
        }

#pragma unroll
        for (int kk = 0; kk < 2; kk++) {
            int kc = kk * 16 + tig * 2;
            uint32_t ah[2][4], alo_[2][4];
#pragma unroll
            for (int mf = 0; mf < 2; mf++) {
                int rb = wM * 32 + mf * 16;
                ah[mf][0]   = *(const uint32_t*)&sA[GSA(0, rb + g,     kc)];
                ah[mf][1]   = *(const uint32_t*)&sA[GSA(0, rb + g + 8, kc)];
                ah[mf][2]   = *(const uint32_t*)&sA[GSA(0, rb + g,     kc + 8)];
                ah[mf][3]   = *(const uint32_t*)&sA[GSA(0, rb + g + 8, kc + 8)];
                alo_[mf][0] = *(const uint32_t*)&sA[GSA(1, rb + g,     kc)];
                alo_[mf][1] = *(const uint32_t*)&sA[GSA(1, rb + g + 8, kc)];
                alo_[mf][2] = *(const uint32_t*)&sA[GSA(1, rb + g,     kc + 8)];
                alo_[mf][3] = *(const uint32_t*)&sA[GSA(1, rb + g + 8, kc + 8)];
            }
#pragma unroll
            for (int j = 0; j < 3; j++)
#pragma unroll
                for (int nf = 0; nf < 4; nf++) {
                    int brw = wN * 32 + nf * 8 + g;
                    uint32_t bh0 = *(const uint32_t*)&sB[GSB(j, 0, brw, kc)];
                    uint32_t bh1 = *(const uint32_t*)&sB[GSB(j, 0, brw, kc + 8)];
                    uint32_t bl0 = *(const uint32_t*)&sB[GSB(j, 1, brw, kc)];
                    uint32_t bl1 = *(const uint32_t*)&sB[GSB(j, 1, brw, kc + 8)];
#pragma unroll
                    for (int mf = 0; mf < 2; mf++) {
                        mma_acc(acc[j][mf][nf], ah[mf],   bh0, bh1);
                        mma_acc(acc[j][mf][nf], ah[mf],   bl0, bl1);
                        mma_acc(acc[j][mf][nf], alo_[mf], bh0, bh1);
                    }
                }
        }
        __syncthreads();
    }

#pragma unroll
    for (int mf = 0; mf < 2; mf++)
#pragma unroll
        for (int nf = 0; nf < 4; nf++) {
            int col = n0 + wN * 32 + nf * 8 + tig * 2;
#pragma unroll
            for (int hh = 0; hh < 2; hh++) {
                int rl = row0 + wM * 32 + mf * 16 + g + hh * 8;
                if (rl < count) {
                    float wc = g_ew[e][rl];
                    float v[2];
#pragma unroll
                    for (int q = 0; q < 2; q++) {
                        int i = hh * 2 + q;
                        float gv = acc[1][mf][nf][i];
                        float xv = acc[2][mf][nf][i];
                        float t = al * (gv * (1.f / (1.f + __expf(-gv))))
                                + (1.f - al) * (xv * (1.f / (1.f + __expf(-xv))));
                        v[q] = wc * acc[0][mf][nf][i] * t;
                    }
                    uint32_t lo;
                    uint32_t hi = pack_hi(v[0], v[1], lo);
                    size_t idx = (size_t)(e * TTOK + rl) * HDIM + col;
                    *(uint32_t*)&g_hh[idx] = hi;
                    *(uint32_t*)&g_hl[idx] = lo;
                }
            }
        }
}

__global__ void __launch_bounds__(256) k_upgate(const float* __restrict__ x,
                                                const float* __restrict__ alpha) {
    extern __shared__ __align__(16) unsigned short sbuf[];
    int e = blockIdx.z;
    int count = g_ecount[e];
    int row0 = blockIdx.x * 128;
    if (row0 >= count) return;
    int n0 = blockIdx.y * 64;
    float al = alpha[e];
    bool hg = (al != 0.f), hx = (al != 1.f);
    if (hg && hx) {
        upgate_gen(sbuf, x, e, count, row0, n0, al);
    } else {
        const __nv_bfloat16* w2 = hg ? g_wg : g_wx;
        float coef = hg ? al : (1.f - al);
        upgate_fast(sbuf, e, count, row0, n0, w2, coef);
    }
}

// ============================================================
// K4: down-proj, BN=128, cp.async double buffer, ldmatrix, atomicAdd.
// sA [2buf][2pl][128][40] = 20480 sh; sB [2buf][2pl][128][40] = 20480 sh.
// ============================================================
__global__ void __launch_bounds__(256) k_down(float* __restrict__ out) {
    extern __shared__ __align__(16) unsigned short sbuf[];
    const int ST = 40;
    unsigned short* sA = sbuf;
    unsigned short* sB = sbuf + 20480;
    int e = blockIdx.z;
    int count = g_ecount[e];
    int row0 = blockIdx.x * 128;
    if (row0 >= count) return;
    int n0 = blockIdx.y * 128;

    int tid = threadIdx.x, lane = tid & 31, w = tid >> 5;
    int wM = w & 3, wN = w >> 2;
    int g = lane >> 2, tig = lane & 3;
    int i8 = lane & 7, seg = lane >> 3;

    int ar = tid >> 1, kh = (tid & 1) * 16;
    const __nv_bfloat16* ahh = g_hh + (size_t)(e * TTOK + row0 + ar) * HDIM + kh;
    const __nv_bfloat16* ahl = g_hl + (size_t)(e * TTOK + row0 + ar) * HDIM + kh;
    const __nv_bfloat16* bsrc[2];
    bsrc[0] = g_wd + ((size_t)(e * 2 + 0) * DDIM + n0 + ar) * HDIM + kh;
    bsrc[1] = g_wd + ((size_t)(e * 2 + 1) * DDIM + n0 + ar) * HDIM + kh;

    uint32_t sAu = smem_u32(sA), sBu = smem_u32(sB);
    int arow_l = (seg & 1) * 8 + i8;
    int acol_l = (seg >> 1) * 8;
    int brow_l = (seg >> 1) * 8 + i8;
    int bcol_l = (seg & 1) * 8;

    float acc[2][8][4];
#pragma unroll
    for (int mf = 0; mf < 2; mf++)
#pragma unroll
        for (int nf = 0; nf < 8; nf++)
#pragma unroll
            for (int q = 0; q < 4; q++) acc[mf][nf][q] = 0.f;

    auto pf = [&](int buf, int k0) {
#pragma unroll
        for (int p = 0; p < 2; p++) {
            const __nv_bfloat16* s = (p ? ahl : ahh) + k0;
            uint32_t d = sAu + 2u * (uint32_t)(((buf * 2 + p) * 128 + ar) * ST + kh);
            cpa16(d, s); cpa16(d + 16, s + 8);
        }
#pragma unroll
        for (int p = 0; p < 2; p++) {
            const __nv_bfloat16* s = bsrc[p] + k0;
            uint32_t d = sBu + 2u * (uint32_t)(((buf * 2 + p) * 128 + ar) * ST + kh);
            cpa16(d, s); cpa16(d + 16, s + 8);
        }
    };

    const int NK = HDIM / 32;   // 44
    pf(0, 0);  CP_COMMIT();
    pf(1, 32); CP_COMMIT();

    for (int c = 0; c < NK; c++) {
        if (c + 1 < NK) CP_WAIT1(); else CP_WAIT0();
        __syncthreads();
        int buf = c & 1;
#pragma unroll
        for (int kk = 0; kk < 2; kk++) {
            uint32_t aF[2][2][4];
#pragma unroll
            for (int p = 0; p < 2; p++)
#pragma unroll
                for (int mf = 0; mf < 2; mf++) {
                    uint32_t ad = sAu + 2u * (uint32_t)(((buf * 2 + p) * 128 + wM * 32 + mf * 16 + arow_l) * ST + kk * 16 + acol_l);
                    LDSM4(aF[p][mf][0], aF[p][mf][1], aF[p][mf][2], aF[p][mf][3], ad);
                }
            uint32_t bF[2][8][2];
#pragma unroll
            for (int p = 0; p < 2; p++)
#pragma unroll
                for (int nfp = 0; nfp < 4; nfp++) {
                    uint32_t bd = sBu + 2u * (uint32_t)(((buf * 2 + p) * 128 + wN * 64 + nfp * 16 + brow_l) * ST + kk * 16 + bcol_l);
                    LDSM4(bF[p][nfp * 2][0], bF[p][nfp * 2][1],
                          bF[p][nfp * 2 + 1][0], bF[p][nfp * 2 + 1][1], bd);
                }
#pragma unroll
            for (int nf = 0; nf < 8; nf++)
#pragma unroll
                for (int mf = 0; mf < 2; mf++) {
                    mma_acc(acc[mf][nf], aF[0][mf], bF[0][nf][0], bF[0][nf][1]);
                    mma_acc(acc[mf][nf], aF[0][mf], bF[1][nf][0], bF[1][nf][1]);
                    mma_acc(acc[mf][nf], aF[1][mf], bF[0][nf][0], bF[0][nf][1]);
                }
        }
        __syncthreads();
        if (c + 2 < NK) { pf(buf, (c + 2) * 32); CP_COMMIT(); }
    }

#pragma unroll
    for (int mf = 0; mf < 2; mf++)
#pragma unroll
        for (int nf = 0; nf < 8; nf++) {
            int col = n0 + wN * 64 + nf * 8 + tig * 2;
#pragma unroll
            for (int hh = 0; hh < 2; hh++) {
                int rl = row0 + wM * 32 + mf * 16 + g + hh * 8;
                if (rl < count) {
                    int tok = g_etok[e][rl];
                    float* orow = out + (size_t)tok * DDIM + col;
                    atomicAdd(&orow[0], acc[mf][nf][hh * 2 + 0]);
                    atomicAdd(&orow[1], acc[mf][nf][hh * 2 + 1]);
                }
            }
        }
}

// ===== K5: LB loss =====
__global__ void k_final(float* __restrict__ out, int out_size) {
    if (threadIdx.x == 0 && blockIdx.x == 0) {
        double s = 0.0;
        for (int e = 0; e < NE; e++) {
            double u = g_usage[e] / (double)TTOK - 1.0 / (double)NE;
            s += u * u;
        }
        float lb = (float)(0.01 * s / (double)NE);
        if (out_size > TTOK * DDIM) out[TTOK * DDIM] = lb;
    }
}

// ============================================================
extern "C" void kernel_launch(void* const* d_in, const int* in_sizes, int n_in,
                              void* d_out, int out_size) {
    const float* x     = (const float*)d_in[0];
    const float* Wr    = (const float*)d_in[1];
    const float* Wg    = (const float*)d_in[2];
    const float* Wu    = (const float*)d_in[3];
    const float* Wxp   = (const float*)d_in[4];
    const float* Wd    = (const float*)d_in[5];
    const float* alpha = (const float*)d_in[6];
    float* out = (float*)d_out;

    const int GEMM_SMEM = 81920;   // 40960 shorts
    cudaFuncSetAttribute(k_upgate, cudaFuncAttributeMaxDynamicSharedMemorySize, GEMM_SMEM);
    cudaFuncSetAttribute(k_down,   cudaFuncAttributeMaxDynamicSharedMemorySize, GEMM_SMEM);

    k_init<<<(TTOK * DDIM + 255) / 256, 256>>>(out);
    k_splitx<<<TTOK * DDIM / 4 / 256, 256>>>(x);

    dim3 tb(32, 8);
    dim3 tg_h(HDIM / 32, DDIM / 32, NE);
    k_tsplit<<<tg_h, tb>>>(Wg,  0, DDIM, HDIM);
    k_tsplit<<<tg_h, tb>>>(Wu,  1, DDIM, HDIM);
    k_tsplit<<<tg_h, tb>>>(Wxp, 2, DDIM, HDIM);
    dim3 tg_d(DDIM / 32, HDIM / 32, NE);
    k_tsplit<<<tg_d, tb>>>(Wd,  3, HDIM, DDIM);

    k_router<<<TTOK / 4, 128>>>(x, Wr);

    dim3 g2(TTOK / 128, HDIM / 64, NE);    // 64 x 22 x 8
    k_upgate<<<g2, 256, GEMM_SMEM>>>(x, alpha);

    dim3 g3(TTOK / 128, DDIM / 128, NE);   // 64 x 8 x 8
    k_down<<<g3, 256, GEMM_SMEM>>>(out);

    k_final<<<1, 32>>>(out, out_size);
}